// round 11
// baseline (speedup 1.0000x reference)
#include <cuda_runtime.h>
#include <cuda_fp16.h>
#include <cstdint>
#include <cstddef>

// NOTE: resubmission of the Round-9 kernel (fp16-pair hoisted-conversion GEMM).
// Round 9 bench failed on infra ("GB300 container failed twice") before this
// design was ever measured.

// Problem constants
#define BATCH   2
#define SEQLEN  1024
#define DMODEL  2048
#define DINNER  4096
#define DSTATE  16
#define DTRANK  128
#define DCONV   4
#define MROWS   (BATCH * SEQLEN)          // 2048
#define XDBLW   (DTRANK + 2 * DSTATE)     // 160

// ---------------- fp32 scratch ----------------
__device__ float g_xz[(size_t)MROWS * 2 * DINNER];
__device__ float g_xc[(size_t)MROWS * DINNER];
__device__ float g_xdbl[(size_t)MROWS * XDBLW];
__device__ float g_delta[(size_t)MROWS * DINNER];
__device__ float g_dummy[32];

// ---------------- fp16-pair scratch: [K/32][rows][128B] (32 hi fp16 | 32 lo fp16) = 4B/elem ----------------
__device__ uint4 g_hid_c [(size_t)MROWS  * DMODEL / 4];
__device__ uint4 g_win_c [(size_t)2 * DINNER * DMODEL / 4];
__device__ uint4 g_xc_c  [(size_t)MROWS  * DINNER / 4];
__device__ uint4 g_wxp_c [(size_t)256    * DINNER / 4];
__device__ uint4 g_xdt_c [(size_t)MROWS  * DTRANK / 4];
__device__ uint4 g_wdt_c [(size_t)DINNER * DTRANK / 4];
__device__ uint4 g_y_c   [(size_t)MROWS  * DINNER / 4];
__device__ uint4 g_wout_c[(size_t)DMODEL * DINNER / 4];

// ---------------- helpers ----------------
__device__ __forceinline__ uint32_t smem_u32(const void* p) {
    uint32_t a;
    asm("{ .reg .u64 t; cvta.to.shared.u64 t, %1; cvt.u32.u64 %0, t; }" : "=r"(a) : "l"(p));
    return a;
}
__device__ __forceinline__ float softplusf(float x) {
    return x > 20.f ? x : log1pf(__expf(x));
}
__device__ __forceinline__ float siluf(float x) {
    return x / (1.f + __expf(-x));
}
// fp16 symmetric split: hi = rn(v), lo = rn(v - hi)
__device__ __forceinline__ void split_f16(float v, __half& hi, __half& lo) {
    hi = __float2half_rn(v);
    lo = __float2half_rn(v - __half2float(hi));
}
__device__ __forceinline__ uint32_t pack_h2(__half a, __half b) {
    return (uint32_t)__half_as_ushort(a) | ((uint32_t)__half_as_ushort(b) << 16);
}

__device__ __forceinline__ void ldsm4(uint32_t (&r)[4], uint32_t addr) {
    asm volatile("ldmatrix.sync.aligned.m8n8.x4.shared.b16 {%0,%1,%2,%3}, [%4];"
                 : "=r"(r[0]), "=r"(r[1]), "=r"(r[2]), "=r"(r[3]) : "r"(addr));
}
__device__ __forceinline__ void mma16816f(float (&c)[4], const uint32_t (&a)[4],
                                          uint32_t b0, uint32_t b1) {
    asm volatile(
        "mma.sync.aligned.m16n8k16.row.col.f32.f16.f16.f32 "
        "{%0,%1,%2,%3}, {%4,%5,%6,%7}, {%8,%9}, {%0,%1,%2,%3};"
        : "+f"(c[0]), "+f"(c[1]), "+f"(c[2]), "+f"(c[3])
        : "r"(a[0]), "r"(a[1]), "r"(a[2]), "r"(a[3]), "r"(b0), "r"(b1));
}
__device__ __forceinline__ void cp16(uint32_t dst, const void* src) {
    asm volatile("cp.async.cg.shared.global [%0], [%1], 16;" :: "r"(dst), "l"(src));
}

__global__ void nop_kernel(float* p) {
    if (threadIdx.x == 0) p[blockIdx.x] = 0.f;
}

// ---------------- convert: fp32 (rows x K, stride ld) -> fp16-pair [K/32][npad][128B] ----------------
__global__ void convert_kernel(const float* __restrict__ src, int ld, int nvalid,
                               int npad, int K, uint8_t* __restrict__ dst)
{
    const int gpr = K >> 3;
    int idx = blockIdx.x * blockDim.x + threadIdx.x;
    if (idx >= npad * gpr) return;
    const int r = idx / gpr;
    const int k0 = (idx - r * gpr) * 8;
    float4 v0 = make_float4(0.f, 0.f, 0.f, 0.f), v1 = v0;
    if (r < nvalid) {
        const float* s = src + (size_t)r * ld + k0;
        v0 = *(const float4*)(s);
        v1 = *(const float4*)(s + 4);
    }
    __half h[8], l[8];
    split_f16(v0.x, h[0], l[0]); split_f16(v0.y, h[1], l[1]);
    split_f16(v0.z, h[2], l[2]); split_f16(v0.w, h[3], l[3]);
    split_f16(v1.x, h[4], l[4]); split_f16(v1.y, h[5], l[5]);
    split_f16(v1.z, h[6], l[6]); split_f16(v1.w, h[7], l[7]);
    uint4 hi = make_uint4(pack_h2(h[0], h[1]), pack_h2(h[2], h[3]),
                          pack_h2(h[4], h[5]), pack_h2(h[6], h[7]));
    uint4 lo = make_uint4(pack_h2(l[0], l[1]), pack_h2(l[2], l[3]),
                          pack_h2(l[4], l[5]), pack_h2(l[6], l[7]));
    // row = 128B: hi half [0,64), lo half [64,128); elem e at byte e*2 / 64+e*2
    size_t off = ((size_t)(k0 >> 5) * npad + r) * 128 + (k0 & 31) * 2;
    *(uint4*)(dst + off)      = hi;
    *(uint4*)(dst + off + 64) = lo;
}

// ---------------- GEMM: cp.async 3-stage, 2 CTAs/SM, fp16-pair operands, 3-term split ----------------
#define NSTAGE  3
#define STAGE_B 32768
#define GEMM_SMEM (NSTAGE * STAGE_B)   // 96KB

template <int EPI>
__global__ void __launch_bounds__(256, 2)
gemm_ca(const uint8_t* __restrict__ Ac, const uint8_t* __restrict__ Bc,
        const float* __restrict__ bias, float* __restrict__ C,
        int M, int Npad, int N, int K)
{
    extern __shared__ __align__(1024) uint8_t smem[];
    const uint32_t sbase = smem_u32(smem);
    const int tid = threadIdx.x;
    const int lid = tid & 31;
    const int wid = tid >> 5;
    const int wm = wid & 1;
    const int wn = wid >> 1;
    const int bm = blockIdx.y * 128;
    const int bn = blockIdx.x * 128;
    const int nch = K >> 5;

    const int ra = tid >> 1, ha = tid & 1;
    const uint8_t* srcA = Ac + (size_t)(bm + ra) * 128 + (size_t)ha * 64;
    const uint8_t* srcB = Bc + (size_t)(bn + ra) * 128 + (size_t)ha * 64;
    const size_t strA = (size_t)M * 128, strB = (size_t)Npad * 128;
    uint32_t doff[4];
    #pragma unroll
    for (int j = 0; j < 4; j++) {
        uint32_t o = (uint32_t)(ra * 128 + ha * 64 + j * 16);
        doff[j] = o ^ ((o >> 3) & 0x70);
    }

    auto issue = [&](int ch) {
        const uint32_t st = sbase + (uint32_t)(ch % NSTAGE) * STAGE_B;
        const uint8_t* sa = srcA + (size_t)ch * strA;
        const uint8_t* sb = srcB + (size_t)ch * strB;
        #pragma unroll
        for (int j = 0; j < 4; j++) {
            cp16(st + doff[j],         sa + j * 16);
            cp16(st + 16384 + doff[j], sb + j * 16);
        }
    };

    #pragma unroll
    for (int ch = 0; ch < 2; ch++) {
        if (ch < nch) issue(ch);
        asm volatile("cp.async.commit_group;" ::: "memory");
    }

    float acc[4][4][4];
    #pragma unroll
    for (int i = 0; i < 4; i++)
        #pragma unroll
        for (int j = 0; j < 4; j++)
            #pragma unroll
            for (int q = 0; q < 4; q++) acc[i][j][q] = 0.f;

    const int lrow = lid & 15;
    const uint32_t lo16 = (uint32_t)((lid >> 4) * 16);
    uint32_t aB[4], bB[2];
    #pragma unroll
    for (int mt = 0; mt < 4; mt++) {
        uint32_t x = (uint32_t)((wm * 64 + mt * 16 + lrow) * 128);
        aB[mt] = x ^ ((x >> 3) & 0x70);
    }
    #pragma unroll
    for (int p = 0; p < 2; p++) {
        uint32_t x = (uint32_t)((wn * 32 + p * 16 + lrow) * 128);
        bB[p] = x ^ ((x >> 3) & 0x70);
    }

    for (int ch = 0; ch < nch; ch++) {
        asm volatile("cp.async.wait_group 1;" ::: "memory");
        __syncthreads();
        if (ch + 2 < nch) issue(ch + 2);
        asm volatile("cp.async.commit_group;" ::: "memory");

        const uint32_t stA = sbase + (uint32_t)(ch % NSTAGE) * STAGE_B;
        const uint32_t stB = stA + 16384;
        #pragma unroll
        for (int s = 0; s < 2; s++) {
            const uint32_t sx = ((uint32_t)s << 5) ^ lo16;
            uint32_t bh[2][4], bl[2][4];
            #pragma unroll
            for (int p = 0; p < 2; p++) {
                ldsm4(bh[p], stB + (bB[p] ^ sx));
                ldsm4(bl[p], stB + (bB[p] ^ sx ^ 64));
            }
            #pragma unroll
            for (int mt = 0; mt < 4; mt++) {
                uint32_t ah[4], al[4];
                ldsm4(ah, stA + (aB[mt] ^ sx));
                ldsm4(al, stA + (aB[mt] ^ sx ^ 64));
                // term-major within mt: 4 independent acc quads between reuses
                #pragma unroll
                for (int nt = 0; nt < 4; nt++) {
                    const int p = nt >> 1, q = nt & 1;
                    mma16816f(acc[mt][nt], ah, bh[p][q], bh[p][q + 2]);
                }
                #pragma unroll
                for (int nt = 0; nt < 4; nt++) {
                    const int p = nt >> 1, q = nt & 1;
                    mma16816f(acc[mt][nt], ah, bl[p][q], bl[p][q + 2]);
                }
                #pragma unroll
                for (int nt = 0; nt < 4; nt++) {
                    const int p = nt >> 1, q = nt & 1;
                    mma16816f(acc[mt][nt], al, bh[p][q], bh[p][q + 2]);
                }
            }
        }
    }
    asm volatile("cp.async.wait_group 0;" ::: "memory");

    #pragma unroll
    for (int mt = 0; mt < 4; mt++) {
        const int m = bm + wm * 64 + mt * 16 + (lid >> 2);
        #pragma unroll
        for (int nt = 0; nt < 4; nt++) {
            const int n = bn + wn * 32 + nt * 8 + (lid & 3) * 2;
            if (n < N) {
                float v0 = acc[mt][nt][0], v1 = acc[mt][nt][1];
                float v2 = acc[mt][nt][2], v3 = acc[mt][nt][3];
                if (EPI == 1) {
                    v0 = softplusf(v0 + bias[n]);     v1 = softplusf(v1 + bias[n + 1]);
                    v2 = softplusf(v2 + bias[n]);     v3 = softplusf(v3 + bias[n + 1]);
                }
                *(float2*)(C + (size_t)m * N + n)       = make_float2(v0, v1);
                *(float2*)(C + (size_t)(m + 8) * N + n) = make_float2(v2, v3);
            }
        }
    }
}

// ---------------- causal depthwise conv (K=4) + SiLU, fp32 + fp16-pair outputs ----------------
__global__ void conv_silu_kernel(const float* __restrict__ xz,
                                 const float* __restrict__ cw,
                                 const float* __restrict__ cb,
                                 float* __restrict__ xc,
                                 uint8_t* __restrict__ xcc)
{
    int idx = blockIdx.x * blockDim.x + threadIdx.x;
    int d  = idx & (DINNER - 1);
    int bl = idx / DINNER;
    int l  = bl & (SEQLEN - 1);

    float acc = cb[d];
    #pragma unroll
    for (int k = 0; k < DCONV; k++) {
        int li = l + k - (DCONV - 1);
        if (li >= 0) {
            float xv = xz[((size_t)(bl + (li - l))) * 2 * DINNER + d];
            acc = fmaf(xv, cw[d * DCONV + k], acc);
        }
    }
    float v = siluf(acc);
    xc[idx] = v;
    __half hi, lo;
    split_f16(v, hi, lo);
    uint8_t* p = xcc + ((size_t)(d >> 5) * MROWS + bl) * 128 + (d & 31) * 2;
    *(__half*)p        = hi;
    *(__half*)(p + 64) = lo;
}

// ---------------- selective scan (writes y as fp16-pair) ----------------
#define SCAN_CH 64
__global__ void __launch_bounds__(64)
scan_kernel(const float* __restrict__ delta,
            const float* __restrict__ xc,
            const float* __restrict__ xdbl,
            const float* __restrict__ xz,
            const float* __restrict__ A,
            const float* __restrict__ Dp,
            uint8_t* __restrict__ yc)
{
    const int d = blockIdx.x * 64 + threadIdx.x;
    const int b = blockIdx.y;

    float st[DSTATE], a[DSTATE];
    #pragma unroll
    for (int n = 0; n < DSTATE; n++) {
        st[n] = 0.f;
        a[n]  = A[(size_t)d * DSTATE + n];
    }
    const float Dd = Dp[d];
    const float a0 = a[0];
    bool fast = true;
    #pragma unroll
    for (int n = 0; n < DSTATE; n++) fast = fast && (a[n] == a0 * (n + 1));

    uint8_t* ycb = yc + (size_t)(d >> 5) * MROWS * 128 + (d & 31) * 2;

    __shared__ float sB[SCAN_CH][DSTATE];
    __shared__ float sC[SCAN_CH][DSTATE];

    for (int t0 = 0; t0 < SEQLEN; t0 += SCAN_CH) {
        __syncthreads();
        for (int i = threadIdx.x; i < SCAN_CH * 2 * DSTATE; i += 64) {
            int tt = i >> 5;
            int c  = i & 31;
            float v = xdbl[((size_t)(b * SEQLEN + t0 + tt)) * XDBLW + DTRANK + c];
            if (c < DSTATE) sB[tt][c] = v;
            else            sC[tt][c - DSTATE] = v;
        }
        __syncthreads();

        for (int tt = 0; tt < SCAN_CH; tt++) {
            const size_t row  = (size_t)(b * SEQLEN + t0 + tt);
            const size_t base = row * DINNER + d;
            float dlt = delta[base];
            float xv  = xc[base];
            float zv  = xz[row * 2 * DINNER + DINNER + d];
            float dx  = dlt * xv;
            float e[DSTATE];
            if (fast) {
                float p  = __expf(dlt * a0);
                float p2 = p * p, p3 = p2 * p, p4 = p2 * p2, p8 = p4 * p4;
                e[0] = p;       e[1] = p2;      e[2] = p3;      e[3] = p4;
                e[4] = p4 * p;  e[5] = p4 * p2; e[6] = p4 * p3; e[7] = p8;
                e[8] = p8 * p;  e[9] = p8 * p2; e[10] = p8 * p3; e[11] = p8 * p4;
                e[12] = e[8] * p4; e[13] = e[9] * p4; e[14] = e[10] * p4; e[15] = p8 * p8;
            } else {
                #pragma unroll
                for (int n = 0; n < DSTATE; n++) e[n] = __expf(dlt * a[n]);
            }
            float yv = 0.f;
            #pragma unroll
            for (int n = 0; n < DSTATE; n++) {
                st[n] = fmaf(e[n], st[n], dx * sB[tt][n]);
                yv    = fmaf(st[n], sC[tt][n], yv);
            }
            float outv = (yv + xv * Dd) * siluf(zv);
            __half hi, lo;
            split_f16(outv, hi, lo);
            uint8_t* p = ycb + row * 128;
            *(__half*)p        = hi;
            *(__half*)(p + 64) = lo;
        }
    }
}

// ---------------- launch ----------------
extern "C" void kernel_launch(void* const* d_in, const int* in_sizes, int n_in,
                              void* d_out, int out_size)
{
    const float* hidden     = (const float*)d_in[0];
    const float* in_proj_w  = (const float*)d_in[1];
    const float* conv_w     = (const float*)d_in[2];
    const float* conv_b     = (const float*)d_in[3];
    const float* x_proj_w   = (const float*)d_in[4];
    const float* dt_proj_w  = (const float*)d_in[5];
    const float* dt_proj_b  = (const float*)d_in[6];
    const float* out_proj_w = (const float*)d_in[7];
    const float* A_in       = (const float*)d_in[8];
    const float* D_param    = (const float*)d_in[9];
    float* out = (float*)d_out;

    static float *p_xz = nullptr, *p_xc = nullptr, *p_xdbl = nullptr,
                 *p_delta = nullptr, *p_dummy = nullptr;
    static uint8_t *p_hidc, *p_winc, *p_xcc, *p_wxpc, *p_xdtc, *p_wdtc, *p_yc, *p_woutc;
    static bool init_done = false;
    if (!init_done) {
        cudaGetSymbolAddress((void**)&p_xz,    g_xz);
        cudaGetSymbolAddress((void**)&p_xc,    g_xc);
        cudaGetSymbolAddress((void**)&p_xdbl,  g_xdbl);
        cudaGetSymbolAddress((void**)&p_delta, g_delta);
        cudaGetSymbolAddress((void**)&p_dummy, g_dummy);
        cudaGetSymbolAddress((void**)&p_hidc,  g_hid_c);
        cudaGetSymbolAddress((void**)&p_winc,  g_win_c);
        cudaGetSymbolAddress((void**)&p_xcc,   g_xc_c);
        cudaGetSymbolAddress((void**)&p_wxpc,  g_wxp_c);
        cudaGetSymbolAddress((void**)&p_xdtc,  g_xdt_c);
        cudaGetSymbolAddress((void**)&p_wdtc,  g_wdt_c);
        cudaGetSymbolAddress((void**)&p_yc,    g_y_c);
        cudaGetSymbolAddress((void**)&p_woutc, g_wout_c);
        cudaFuncSetAttribute(gemm_ca<0>, cudaFuncAttributeMaxDynamicSharedMemorySize, GEMM_SMEM);
        cudaFuncSetAttribute(gemm_ca<1>, cudaFuncAttributeMaxDynamicSharedMemorySize, GEMM_SMEM);
        init_done = true;
    }

    // #1, #2: converts needed by in_proj; #3: nop -> in_proj lands at captured launch #4
    convert_kernel<<<(MROWS * (DMODEL >> 3) + 255) / 256, 256>>>(hidden, DMODEL, MROWS, MROWS, DMODEL, p_hidc);
    convert_kernel<<<(2 * DINNER * (DMODEL >> 3) + 255) / 256, 256>>>(in_proj_w, DMODEL, 2 * DINNER, 2 * DINNER, DMODEL, p_winc);
    nop_kernel<<<1, 32>>>(p_dummy);

    // #4) in_proj -> xz (fp32)
    gemm_ca<0><<<dim3(2 * DINNER / 128, MROWS / 128), 256, GEMM_SMEM>>>(
        p_hidc, p_winc, nullptr, p_xz, MROWS, 2 * DINNER, 2 * DINNER, DMODEL);

    // conv + SiLU -> xc (fp32) + xcc (fp16-pair)
    conv_silu_kernel<<<(MROWS * DINNER) / 256, 256>>>(p_xz, conv_w, conv_b, p_xc, p_xcc);

    // x_proj
    convert_kernel<<<(256 * (DINNER >> 3) + 255) / 256, 256>>>(x_proj_w, DINNER, XDBLW, 256, DINNER, p_wxpc);
    gemm_ca<0><<<dim3(2, MROWS / 128), 256, GEMM_SMEM>>>(
        p_xcc, p_wxpc, nullptr, p_xdbl, MROWS, 256, XDBLW, DINNER);

    // dt_proj
    convert_kernel<<<(MROWS * (DTRANK >> 3) + 255) / 256, 256>>>(p_xdbl, XDBLW, MROWS, MROWS, DTRANK, p_xdtc);
    convert_kernel<<<(DINNER * (DTRANK >> 3) + 255) / 256, 256>>>(dt_proj_w, DTRANK, DINNER, DINNER, DTRANK, p_wdtc);
    gemm_ca<1><<<dim3(DINNER / 128, MROWS / 128), 256, GEMM_SMEM>>>(
        p_xdtc, p_wdtc, dt_proj_b, p_delta, MROWS, DINNER, DINNER, DTRANK);

    // scan -> yc (fp16-pair)
    scan_kernel<<<dim3(DINNER / 64, BATCH), 64>>>(
        p_delta, p_xc, p_xdbl, p_xz, A_in, D_param, p_yc);

    // out_proj
    convert_kernel<<<(DMODEL * (DINNER >> 3) + 255) / 256, 256>>>(out_proj_w, DINNER, DMODEL, DMODEL, DINNER, p_woutc);
    gemm_ca<0><<<dim3(DMODEL / 128, MROWS / 128), 256, GEMM_SMEM>>>(
        p_yc, p_woutc, nullptr, out, MROWS, DMODEL, DMODEL, DINNER);
}

// round 14
// speedup vs baseline: 1.5297x; 1.5297x over previous
#include <cuda_runtime.h>
#include <cuda_fp16.h>
#include <cstdint>
#include <cstddef>

// R14: identical to R12/R13 except the scan's shared staging arrays are
// __align__(16) — cp.async.cg 16B requires 16B-aligned SMEM destinations;
// plain __shared__ float arrays only guarantee 4B. Suspected cause of the
// R12/R13 container crashes.

// Problem constants
#define BATCH   2
#define SEQLEN  1024
#define DMODEL  2048
#define DINNER  4096
#define DSTATE  16
#define DTRANK  128
#define DCONV   4
#define MROWS   (BATCH * SEQLEN)          // 2048
#define XDBLW   (DTRANK + 2 * DSTATE)     // 160
#define XSPLIT  8                          // split-K ways for x_proj

// ---------------- fp32 scratch ----------------
__device__ float g_xz[(size_t)MROWS * 2 * DINNER];
__device__ float g_xc[(size_t)MROWS * DINNER];
__device__ float g_xdbl[(size_t)MROWS * XDBLW];
__device__ float g_xpart[(size_t)XSPLIT * MROWS * XDBLW];
__device__ float g_delta[(size_t)MROWS * DINNER];
__device__ float g_dummy[32];

// ---------------- fp16-pair scratch: [K/32][rows][128B] (32 hi fp16 | 32 lo fp16) ----------------
__device__ uint4 g_hid_c [(size_t)MROWS  * DMODEL / 4];
__device__ uint4 g_win_c [(size_t)2 * DINNER * DMODEL / 4];
__device__ uint4 g_xc_c  [(size_t)MROWS  * DINNER / 4];
__device__ uint4 g_wxp_c [(size_t)256    * DINNER / 4];
__device__ uint4 g_xdt_c [(size_t)MROWS  * DTRANK / 4];
__device__ uint4 g_wdt_c [(size_t)DINNER * DTRANK / 4];
__device__ uint4 g_y_c   [(size_t)MROWS  * DINNER / 4];
__device__ uint4 g_wout_c[(size_t)DMODEL * DINNER / 4];

// ---------------- helpers ----------------
__device__ __forceinline__ uint32_t smem_u32(const void* p) {
    uint32_t a;
    asm("{ .reg .u64 t; cvta.to.shared.u64 t, %1; cvt.u32.u64 %0, t; }" : "=r"(a) : "l"(p));
    return a;
}
__device__ __forceinline__ float softplusf(float x) {
    return x > 20.f ? x : log1pf(__expf(x));
}
__device__ __forceinline__ float siluf(float x) {
    return x / (1.f + __expf(-x));
}
__device__ __forceinline__ void split_f16(float v, __half& hi, __half& lo) {
    hi = __float2half_rn(v);
    lo = __float2half_rn(v - __half2float(hi));
}
__device__ __forceinline__ uint32_t pack_h2(__half a, __half b) {
    return (uint32_t)__half_as_ushort(a) | ((uint32_t)__half_as_ushort(b) << 16);
}

__device__ __forceinline__ void ldsm4(uint32_t (&r)[4], uint32_t addr) {
    asm volatile("ldmatrix.sync.aligned.m8n8.x4.shared.b16 {%0,%1,%2,%3}, [%4];"
                 : "=r"(r[0]), "=r"(r[1]), "=r"(r[2]), "=r"(r[3]) : "r"(addr));
}
__device__ __forceinline__ void mma16816f(float (&c)[4], const uint32_t (&a)[4],
                                          uint32_t b0, uint32_t b1) {
    asm volatile(
        "mma.sync.aligned.m16n8k16.row.col.f32.f16.f16.f32 "
        "{%0,%1,%2,%3}, {%4,%5,%6,%7}, {%8,%9}, {%0,%1,%2,%3};"
        : "+f"(c[0]), "+f"(c[1]), "+f"(c[2]), "+f"(c[3])
        : "r"(a[0]), "r"(a[1]), "r"(a[2]), "r"(a[3]), "r"(b0), "r"(b1));
}
__device__ __forceinline__ void cp16(uint32_t dst, const void* src) {
    asm volatile("cp.async.cg.shared.global [%0], [%1], 16;" :: "r"(dst), "l"(src));
}

__global__ void nop_kernel(float* p) {
    if (threadIdx.x == 0) p[blockIdx.x] = 0.f;
}

// ---------------- convert: fp32 (rows x K, stride ld) -> fp16-pair [K/32][npad][128B] ----------------
__global__ void convert_kernel(const float* __restrict__ src, int ld, int nvalid,
                               int npad, int K, uint8_t* __restrict__ dst)
{
    const int gpr = K >> 3;
    int idx = blockIdx.x * blockDim.x + threadIdx.x;
    if (idx >= npad * gpr) return;
    const int r = idx / gpr;
    const int k0 = (idx - r * gpr) * 8;
    float4 v0 = make_float4(0.f, 0.f, 0.f, 0.f), v1 = v0;
    if (r < nvalid) {
        const float* s = src + (size_t)r * ld + k0;
        v0 = *(const float4*)(s);
        v1 = *(const float4*)(s + 4);
    }
    __half h[8], l[8];
    split_f16(v0.x, h[0], l[0]); split_f16(v0.y, h[1], l[1]);
    split_f16(v0.z, h[2], l[2]); split_f16(v0.w, h[3], l[3]);
    split_f16(v1.x, h[4], l[4]); split_f16(v1.y, h[5], l[5]);
    split_f16(v1.z, h[6], l[6]); split_f16(v1.w, h[7], l[7]);
    uint4 hi = make_uint4(pack_h2(h[0], h[1]), pack_h2(h[2], h[3]),
                          pack_h2(h[4], h[5]), pack_h2(h[6], h[7]));
    uint4 lo = make_uint4(pack_h2(l[0], l[1]), pack_h2(l[2], l[3]),
                          pack_h2(l[4], l[5]), pack_h2(l[6], l[7]));
    size_t off = ((size_t)(k0 >> 5) * npad + r) * 128 + (k0 & 31) * 2;
    *(uint4*)(dst + off)      = hi;
    *(uint4*)(dst + off + 64) = lo;
}

// ---------------- GEMM: cp.async 3-stage, 2 CTAs/SM, fp16-pair operands, 3-term split ----------------
// SPLIT=1: blockIdx.z selects a K/XSPLIT-wide K slice; raw partials to C + z*M*N.
#define NSTAGE  3
#define STAGE_B 32768
#define GEMM_SMEM (NSTAGE * STAGE_B)   // 96KB

template <int EPI, int SPLIT>
__global__ void __launch_bounds__(256, 2)
gemm_ca(const uint8_t* __restrict__ Ac, const uint8_t* __restrict__ Bc,
        const float* __restrict__ bias, float* __restrict__ C,
        int M, int Npad, int N, int K)
{
    extern __shared__ __align__(1024) uint8_t smem[];
    const uint32_t sbase = smem_u32(smem);
    const int tid = threadIdx.x;
    const int lid = tid & 31;
    const int wid = tid >> 5;
    const int wm = wid & 1;
    const int wn = wid >> 1;
    const int bm = blockIdx.y * 128;
    const int bn = blockIdx.x * 128;
    const int nch = K >> 5;

    const int ra = tid >> 1, ha = tid & 1;
    const size_t strA = (size_t)M * 128, strB = (size_t)Npad * 128;
    const uint8_t* srcA = Ac + (size_t)(bm + ra) * 128 + (size_t)ha * 64;
    const uint8_t* srcB = Bc + (size_t)(bn + ra) * 128 + (size_t)ha * 64;
    if (SPLIT) {
        srcA += (size_t)blockIdx.z * nch * strA;
        srcB += (size_t)blockIdx.z * nch * strB;
        C    += (size_t)blockIdx.z * M * N;
    }
    uint32_t doff[4];
    #pragma unroll
    for (int j = 0; j < 4; j++) {
        uint32_t o = (uint32_t)(ra * 128 + ha * 64 + j * 16);
        doff[j] = o ^ ((o >> 3) & 0x70);
    }

    auto issue = [&](int ch) {
        const uint32_t st = sbase + (uint32_t)(ch % NSTAGE) * STAGE_B;
        const uint8_t* sa = srcA + (size_t)ch * strA;
        const uint8_t* sb = srcB + (size_t)ch * strB;
        #pragma unroll
        for (int j = 0; j < 4; j++) {
            cp16(st + doff[j],         sa + j * 16);
            cp16(st + 16384 + doff[j], sb + j * 16);
        }
    };

    #pragma unroll
    for (int ch = 0; ch < 2; ch++) {
        if (ch < nch) issue(ch);
        asm volatile("cp.async.commit_group;" ::: "memory");
    }

    float acc[4][4][4];
    #pragma unroll
    for (int i = 0; i < 4; i++)
        #pragma unroll
        for (int j = 0; j < 4; j++)
            #pragma unroll
            for (int q = 0; q < 4; q++) acc[i][j][q] = 0.f;

    const int lrow = lid & 15;
    const uint32_t lo16 = (uint32_t)((lid >> 4) * 16);
    uint32_t aB[4], bB[2];
    #pragma unroll
    for (int mt = 0; mt < 4; mt++) {
        uint32_t x = (uint32_t)((wm * 64 + mt * 16 + lrow) * 128);
        aB[mt] = x ^ ((x >> 3) & 0x70);
    }
    #pragma unroll
    for (int p = 0; p < 2; p++) {
        uint32_t x = (uint32_t)((wn * 32 + p * 16 + lrow) * 128);
        bB[p] = x ^ ((x >> 3) & 0x70);
    }

    for (int ch = 0; ch < nch; ch++) {
        asm volatile("cp.async.wait_group 1;" ::: "memory");
        __syncthreads();
        if (ch + 2 < nch) issue(ch + 2);
        asm volatile("cp.async.commit_group;" ::: "memory");

        const uint32_t stA = sbase + (uint32_t)(ch % NSTAGE) * STAGE_B;
        const uint32_t stB = stA + 16384;
        #pragma unroll
        for (int s = 0; s < 2; s++) {
            const uint32_t sx = ((uint32_t)s << 5) ^ lo16;
            uint32_t bh[2][4], bl[2][4];
            #pragma unroll
            for (int p = 0; p < 2; p++) {
                ldsm4(bh[p], stB + (bB[p] ^ sx));
                ldsm4(bl[p], stB + (bB[p] ^ sx ^ 64));
            }
            #pragma unroll
            for (int mt = 0; mt < 4; mt++) {
                uint32_t ah[4], al[4];
                ldsm4(ah, stA + (aB[mt] ^ sx));
                ldsm4(al, stA + (aB[mt] ^ sx ^ 64));
                #pragma unroll
                for (int nt = 0; nt < 4; nt++) {
                    const int p = nt >> 1, q = nt & 1;
                    mma16816f(acc[mt][nt], ah, bh[p][q], bh[p][q + 2]);
                }
                #pragma unroll
                for (int nt = 0; nt < 4; nt++) {
                    const int p = nt >> 1, q = nt & 1;
                    mma16816f(acc[mt][nt], ah, bl[p][q], bl[p][q + 2]);
                }
                #pragma unroll
                for (int nt = 0; nt < 4; nt++) {
                    const int p = nt >> 1, q = nt & 1;
                    mma16816f(acc[mt][nt], al, bh[p][q], bh[p][q + 2]);
                }
            }
        }
    }
    asm volatile("cp.async.wait_group 0;" ::: "memory");

    #pragma unroll
    for (int mt = 0; mt < 4; mt++) {
        const int m = bm + wm * 64 + mt * 16 + (lid >> 2);
        #pragma unroll
        for (int nt = 0; nt < 4; nt++) {
            const int n = bn + wn * 32 + nt * 8 + (lid & 3) * 2;
            if (n < N) {
                float v0 = acc[mt][nt][0], v1 = acc[mt][nt][1];
                float v2 = acc[mt][nt][2], v3 = acc[mt][nt][3];
                if (EPI == 1) {
                    v0 = softplusf(v0 + bias[n]);     v1 = softplusf(v1 + bias[n + 1]);
                    v2 = softplusf(v2 + bias[n]);     v3 = softplusf(v3 + bias[n + 1]);
                }
                *(float2*)(C + (size_t)m * N + n)       = make_float2(v0, v1);
                *(float2*)(C + (size_t)(m + 8) * N + n) = make_float2(v2, v3);
            }
        }
    }
}

// ---------------- x_proj split-K reduction: sum partials -> xdbl fp32 + xdt fp16-pair ----------------
__global__ void reduce_xproj(const float* __restrict__ part,
                             float* __restrict__ xdbl,
                             uint8_t* __restrict__ xdt)
{
    int idx = blockIdx.x * blockDim.x + threadIdx.x;
    if (idx >= MROWS * XDBLW) return;
    int m = idx / XDBLW, n = idx - m * XDBLW;
    float s = 0.f;
    #pragma unroll
    for (int p = 0; p < XSPLIT; p++)
        s += part[(size_t)p * MROWS * XDBLW + idx];
    xdbl[idx] = s;
    if (n < DTRANK) {
        __half hi, lo;
        split_f16(s, hi, lo);
        uint8_t* q = xdt + ((size_t)(n >> 5) * MROWS + m) * 128 + (n & 31) * 2;
        *(__half*)q        = hi;
        *(__half*)(q + 64) = lo;
    }
}

// ---------------- causal depthwise conv (K=4) + SiLU, fp32 + fp16-pair outputs ----------------
__global__ void conv_silu_kernel(const float* __restrict__ xz,
                                 const float* __restrict__ cw,
                                 const float* __restrict__ cb,
                                 float* __restrict__ xc,
                                 uint8_t* __restrict__ xcc)
{
    int idx = blockIdx.x * blockDim.x + threadIdx.x;
    int d  = idx & (DINNER - 1);
    int bl = idx / DINNER;
    int l  = bl & (SEQLEN - 1);

    float acc = cb[d];
    #pragma unroll
    for (int k = 0; k < DCONV; k++) {
        int li = l + k - (DCONV - 1);
        if (li >= 0) {
            float xv = xz[((size_t)(bl + (li - l))) * 2 * DINNER + d];
            acc = fmaf(xv, cw[d * DCONV + k], acc);
        }
    }
    float v = siluf(acc);
    xc[idx] = v;
    __half hi, lo;
    split_f16(v, hi, lo);
    uint8_t* p = xcc + ((size_t)(d >> 5) * MROWS + bl) * 128 + (d & 31) * 2;
    *(__half*)p        = hi;
    *(__half*)(p + 64) = lo;
}

// ---------------- selective scan: cp.async staged, double-buffered ----------------
#define SC_T 16
__global__ void __launch_bounds__(64)
scan_kernel(const float* __restrict__ delta,
            const float* __restrict__ xc,
            const float* __restrict__ xz,
            const float* __restrict__ xdbl,
            const float* __restrict__ A,
            const float* __restrict__ Dp,
            uint8_t* __restrict__ yc)
{
    const int tid = threadIdx.x;
    const int d0 = blockIdx.x * 64;
    const int d  = d0 + tid;
    const int b  = blockIdx.y;

    // 16B alignment REQUIRED for cp.async destinations
    __shared__ __align__(16) float sD[2][SC_T][64];
    __shared__ __align__(16) float sX[2][SC_T][64];
    __shared__ __align__(16) float sZ[2][SC_T][64];
    __shared__ __align__(16) float sB[2][SC_T][16];
    __shared__ __align__(16) float sC[2][SC_T][16];

    float st[DSTATE], a[DSTATE];
    #pragma unroll
    for (int n = 0; n < DSTATE; n++) {
        st[n] = 0.f;
        a[n]  = A[(size_t)d * DSTATE + n];
    }
    const float Dd = Dp[d];
    const float a0 = a[0];
    bool fast = true;
    #pragma unroll
    for (int n = 0; n < DSTATE; n++) fast = fast && (a[n] == a0 * (n + 1));

    uint8_t* ycb = yc + (size_t)(d >> 5) * MROWS * 128 + (d & 31) * 2;

    auto stage = [&](int buf, int t0) {
        #pragma unroll
        for (int j = tid; j < SC_T * 16; j += 64) {
            int row = j >> 4, sec = j & 15;
            size_t r = (size_t)(b * SEQLEN + t0 + row);
            cp16(smem_u32(&sD[buf][row][sec * 4]), delta + r * DINNER + d0 + sec * 4);
            cp16(smem_u32(&sX[buf][row][sec * 4]), xc + r * DINNER + d0 + sec * 4);
            cp16(smem_u32(&sZ[buf][row][sec * 4]), xz + r * 2 * DINNER + DINNER + d0 + sec * 4);
        }
        {
            int row = tid >> 2, sec = tid & 3;   // 64 = SC_T*4 exactly
            size_t r = (size_t)(b * SEQLEN + t0 + row);
            cp16(smem_u32(&sB[buf][row][sec * 4]), xdbl + r * XDBLW + DTRANK + sec * 4);
            cp16(smem_u32(&sC[buf][row][sec * 4]), xdbl + r * XDBLW + DTRANK + DSTATE + sec * 4);
        }
    };

    stage(0, 0);
    asm volatile("cp.async.commit_group;" ::: "memory");
    int buf = 0;

    for (int ch = 0; ch < SEQLEN / SC_T; ch++) {
        if (ch + 1 < SEQLEN / SC_T) stage(buf ^ 1, (ch + 1) * SC_T);
        asm volatile("cp.async.commit_group;" ::: "memory");
        asm volatile("cp.async.wait_group 1;" ::: "memory");
        __syncthreads();

        const int t0 = ch * SC_T;
        #pragma unroll 4
        for (int tt = 0; tt < SC_T; tt++) {
            float dlt = sD[buf][tt][tid];
            float xv  = sX[buf][tt][tid];
            float zv  = sZ[buf][tt][tid];
            float dx  = dlt * xv;
            float e[DSTATE];
            if (fast) {
                float p  = __expf(dlt * a0);
                float p2 = p * p, p3 = p2 * p, p4 = p2 * p2, p8 = p4 * p4;
                e[0] = p;       e[1] = p2;      e[2] = p3;      e[3] = p4;
                e[4] = p4 * p;  e[5] = p4 * p2; e[6] = p4 * p3; e[7] = p8;
                e[8] = p8 * p;  e[9] = p8 * p2; e[10] = p8 * p3; e[11] = p8 * p4;
                e[12] = e[8] * p4; e[13] = e[9] * p4; e[14] = e[10] * p4; e[15] = p8 * p8;
            } else {
                #pragma unroll
                for (int n = 0; n < DSTATE; n++) e[n] = __expf(dlt * a[n]);
            }
            float yv = 0.f;
            #pragma unroll
            for (int n = 0; n < DSTATE; n++) {
                st[n] = fmaf(e[n], st[n], dx * sB[buf][tt][n]);
                yv    = fmaf(st[n], sC[buf][tt][n], yv);
            }
            float outv = (yv + xv * Dd) * siluf(zv);
            __half hi, lo;
            split_f16(outv, hi, lo);
            uint8_t* p = ycb + (size_t)(b * SEQLEN + t0 + tt) * 128;
            *(__half*)p        = hi;
            *(__half*)(p + 64) = lo;
        }
        __syncthreads();
        buf ^= 1;
    }
}

// ---------------- launch ----------------
extern "C" void kernel_launch(void* const* d_in, const int* in_sizes, int n_in,
                              void* d_out, int out_size)
{
    const float* hidden     = (const float*)d_in[0];
    const float* in_proj_w  = (const float*)d_in[1];
    const float* conv_w     = (const float*)d_in[2];
    const float* conv_b     = (const float*)d_in[3];
    const float* x_proj_w   = (const float*)d_in[4];
    const float* dt_proj_w  = (const float*)d_in[5];
    const float* dt_proj_b  = (const float*)d_in[6];
    const float* out_proj_w = (const float*)d_in[7];
    const float* A_in       = (const float*)d_in[8];
    const float* D_param    = (const float*)d_in[9];
    float* out = (float*)d_out;

    static float *p_xz = nullptr, *p_xc = nullptr, *p_xdbl = nullptr,
                 *p_xpart = nullptr, *p_delta = nullptr, *p_dummy = nullptr;
    static uint8_t *p_hidc, *p_winc, *p_xcc, *p_wxpc, *p_xdtc, *p_wdtc, *p_yc, *p_woutc;
    static bool init_done = false;
    if (!init_done) {
        cudaGetSymbolAddress((void**)&p_xz,    g_xz);
        cudaGetSymbolAddress((void**)&p_xc,    g_xc);
        cudaGetSymbolAddress((void**)&p_xdbl,  g_xdbl);
        cudaGetSymbolAddress((void**)&p_xpart, g_xpart);
        cudaGetSymbolAddress((void**)&p_delta, g_delta);
        cudaGetSymbolAddress((void**)&p_dummy, g_dummy);
        cudaGetSymbolAddress((void**)&p_hidc,  g_hid_c);
        cudaGetSymbolAddress((void**)&p_winc,  g_win_c);
        cudaGetSymbolAddress((void**)&p_xcc,   g_xc_c);
        cudaGetSymbolAddress((void**)&p_wxpc,  g_wxp_c);
        cudaGetSymbolAddress((void**)&p_xdtc,  g_xdt_c);
        cudaGetSymbolAddress((void**)&p_wdtc,  g_wdt_c);
        cudaGetSymbolAddress((void**)&p_yc,    g_y_c);
        cudaGetSymbolAddress((void**)&p_woutc, g_wout_c);
        cudaFuncSetAttribute((const void*)gemm_ca<0,0>, cudaFuncAttributeMaxDynamicSharedMemorySize, GEMM_SMEM);
        cudaFuncSetAttribute((const void*)gemm_ca<1,0>, cudaFuncAttributeMaxDynamicSharedMemorySize, GEMM_SMEM);
        cudaFuncSetAttribute((const void*)gemm_ca<0,1>, cudaFuncAttributeMaxDynamicSharedMemorySize, GEMM_SMEM);
        init_done = true;
    }

    // #1, #2 converts; #3 nop -> in_proj at captured launch #4
    convert_kernel<<<(MROWS * (DMODEL >> 3) + 255) / 256, 256>>>(hidden, DMODEL, MROWS, MROWS, DMODEL, p_hidc);
    convert_kernel<<<(2 * DINNER * (DMODEL >> 3) + 255) / 256, 256>>>(in_proj_w, DMODEL, 2 * DINNER, 2 * DINNER, DMODEL, p_winc);
    nop_kernel<<<1, 32>>>(p_dummy);

    // #4) in_proj -> xz (fp32)
    gemm_ca<0,0><<<dim3(2 * DINNER / 128, MROWS / 128), 256, GEMM_SMEM>>>(
        p_hidc, p_winc, nullptr, p_xz, MROWS, 2 * DINNER, 2 * DINNER, DMODEL);

    // conv + SiLU -> xc (fp32) + xcc (fp16-pair)
    conv_silu_kernel<<<(MROWS * DINNER) / 256, 256>>>(p_xz, conv_w, conv_b, p_xc, p_xcc);

    // x_proj: split-K x8 -> partials -> reduce (also emits xdt fp16-pair)
    convert_kernel<<<(256 * (DINNER >> 3) + 255) / 256, 256>>>(x_proj_w, DINNER, XDBLW, 256, DINNER, p_wxpc);
    gemm_ca<0,1><<<dim3(2, MROWS / 128, XSPLIT), 256, GEMM_SMEM>>>(
        p_xcc, p_wxpc, nullptr, p_xpart, MROWS, 256, XDBLW, DINNER / XSPLIT);
    reduce_xproj<<<(MROWS * XDBLW + 255) / 256, 256>>>(p_xpart, p_xdbl, p_xdtc);

    // dt_proj + bias + softplus -> delta (fp32)
    convert_kernel<<<(DINNER * (DTRANK >> 3) + 255) / 256, 256>>>(dt_proj_w, DTRANK, DINNER, DINNER, DTRANK, p_wdtc);
    gemm_ca<1,0><<<dim3(DINNER / 128, MROWS / 128), 256, GEMM_SMEM>>>(
        p_xdtc, p_wdtc, dt_proj_b, p_delta, MROWS, DINNER, DINNER, DTRANK);

    // scan -> yc (fp16-pair)
    scan_kernel<<<dim3(DINNER / 64, BATCH), 64>>>(
        p_delta, p_xc, p_xz, p_xdbl, A_in, D_param, p_yc);

    // out_proj
    convert_kernel<<<(DMODEL * (DINNER >> 3) + 255) / 256, 256>>>(out_proj_w, DINNER, DMODEL, DMODEL, DINNER, p_woutc);
    gemm_ca<0,0><<<dim3(DMODEL / 128, MROWS / 128), 256, GEMM_SMEM>>>(
        p_yc, p_woutc, nullptr, out, MROWS, DMODEL, DMODEL, DINNER);
}

// round 15
// speedup vs baseline: 1.8233x; 1.1919x over previous
#include <cuda_runtime.h>
#include <cuda_fp16.h>
#include <cstdint>
#include <cstddef>

// R15: TERMS template param — in_proj/out_proj use 2-term fp16 split
// (ah*bh + ah*bl; A-residual dropped, error ~2^-12), x_proj/dt_proj keep 3-term.

// Problem constants
#define BATCH   2
#define SEQLEN  1024
#define DMODEL  2048
#define DINNER  4096
#define DSTATE  16
#define DTRANK  128
#define DCONV   4
#define MROWS   (BATCH * SEQLEN)          // 2048
#define XDBLW   (DTRANK + 2 * DSTATE)     // 160
#define XSPLIT  8                          // split-K ways for x_proj

// ---------------- fp32 scratch ----------------
__device__ float g_xz[(size_t)MROWS * 2 * DINNER];
__device__ float g_xc[(size_t)MROWS * DINNER];
__device__ float g_xdbl[(size_t)MROWS * XDBLW];
__device__ float g_xpart[(size_t)XSPLIT * MROWS * XDBLW];
__device__ float g_delta[(size_t)MROWS * DINNER];
__device__ float g_dummy[32];

// ---------------- fp16-pair scratch: [K/32][rows][128B] (32 hi fp16 | 32 lo fp16) ----------------
__device__ uint4 g_hid_c [(size_t)MROWS  * DMODEL / 4];
__device__ uint4 g_win_c [(size_t)2 * DINNER * DMODEL / 4];
__device__ uint4 g_xc_c  [(size_t)MROWS  * DINNER / 4];
__device__ uint4 g_wxp_c [(size_t)256    * DINNER / 4];
__device__ uint4 g_xdt_c [(size_t)MROWS  * DTRANK / 4];
__device__ uint4 g_wdt_c [(size_t)DINNER * DTRANK / 4];
__device__ uint4 g_y_c   [(size_t)MROWS  * DINNER / 4];
__device__ uint4 g_wout_c[(size_t)DMODEL * DINNER / 4];

// ---------------- helpers ----------------
__device__ __forceinline__ uint32_t smem_u32(const void* p) {
    uint32_t a;
    asm("{ .reg .u64 t; cvta.to.shared.u64 t, %1; cvt.u32.u64 %0, t; }" : "=r"(a) : "l"(p));
    return a;
}
__device__ __forceinline__ float softplusf(float x) {
    return x > 20.f ? x : log1pf(__expf(x));
}
__device__ __forceinline__ float siluf(float x) {
    return x / (1.f + __expf(-x));
}
__device__ __forceinline__ void split_f16(float v, __half& hi, __half& lo) {
    hi = __float2half_rn(v);
    lo = __float2half_rn(v - __half2float(hi));
}
__device__ __forceinline__ uint32_t pack_h2(__half a, __half b) {
    return (uint32_t)__half_as_ushort(a) | ((uint32_t)__half_as_ushort(b) << 16);
}

__device__ __forceinline__ void ldsm4(uint32_t (&r)[4], uint32_t addr) {
    asm volatile("ldmatrix.sync.aligned.m8n8.x4.shared.b16 {%0,%1,%2,%3}, [%4];"
                 : "=r"(r[0]), "=r"(r[1]), "=r"(r[2]), "=r"(r[3]) : "r"(addr));
}
__device__ __forceinline__ void mma16816f(float (&c)[4], const uint32_t (&a)[4],
                                          uint32_t b0, uint32_t b1) {
    asm volatile(
        "mma.sync.aligned.m16n8k16.row.col.f32.f16.f16.f32 "
        "{%0,%1,%2,%3}, {%4,%5,%6,%7}, {%8,%9}, {%0,%1,%2,%3};"
        : "+f"(c[0]), "+f"(c[1]), "+f"(c[2]), "+f"(c[3])
        : "r"(a[0]), "r"(a[1]), "r"(a[2]), "r"(a[3]), "r"(b0), "r"(b1));
}
__device__ __forceinline__ void cp16(uint32_t dst, const void* src) {
    asm volatile("cp.async.cg.shared.global [%0], [%1], 16;" :: "r"(dst), "l"(src));
}

__global__ void nop_kernel(float* p) {
    if (threadIdx.x == 0) p[blockIdx.x] = 0.f;
}

// ---------------- convert: fp32 (rows x K, stride ld) -> fp16-pair [K/32][npad][128B] ----------------
__global__ void convert_kernel(const float* __restrict__ src, int ld, int nvalid,
                               int npad, int K, uint8_t* __restrict__ dst)
{
    const int gpr = K >> 3;
    int idx = blockIdx.x * blockDim.x + threadIdx.x;
    if (idx >= npad * gpr) return;
    const int r = idx / gpr;
    const int k0 = (idx - r * gpr) * 8;
    float4 v0 = make_float4(0.f, 0.f, 0.f, 0.f), v1 = v0;
    if (r < nvalid) {
        const float* s = src + (size_t)r * ld + k0;
        v0 = *(const float4*)(s);
        v1 = *(const float4*)(s + 4);
    }
    __half h[8], l[8];
    split_f16(v0.x, h[0], l[0]); split_f16(v0.y, h[1], l[1]);
    split_f16(v0.z, h[2], l[2]); split_f16(v0.w, h[3], l[3]);
    split_f16(v1.x, h[4], l[4]); split_f16(v1.y, h[5], l[5]);
    split_f16(v1.z, h[6], l[6]); split_f16(v1.w, h[7], l[7]);
    uint4 hi = make_uint4(pack_h2(h[0], h[1]), pack_h2(h[2], h[3]),
                          pack_h2(h[4], h[5]), pack_h2(h[6], h[7]));
    uint4 lo = make_uint4(pack_h2(l[0], l[1]), pack_h2(l[2], l[3]),
                          pack_h2(l[4], l[5]), pack_h2(l[6], l[7]));
    size_t off = ((size_t)(k0 >> 5) * npad + r) * 128 + (k0 & 31) * 2;
    *(uint4*)(dst + off)      = hi;
    *(uint4*)(dst + off + 64) = lo;
}

// ---------------- GEMM: cp.async 3-stage, 2 CTAs/SM, fp16-pair operands ----------------
// TERMS=3: ah*bh + ah*bl + al*bh ; TERMS=2: ah*bh + ah*bl (A residual dropped)
// SPLIT=1: blockIdx.z selects a K/XSPLIT-wide K slice; raw partials to C + z*M*N.
#define NSTAGE  3
#define STAGE_B 32768
#define GEMM_SMEM (NSTAGE * STAGE_B)   // 96KB

template <int EPI, int SPLIT, int TERMS>
__global__ void __launch_bounds__(256, 2)
gemm_ca(const uint8_t* __restrict__ Ac, const uint8_t* __restrict__ Bc,
        const float* __restrict__ bias, float* __restrict__ C,
        int M, int Npad, int N, int K)
{
    extern __shared__ __align__(1024) uint8_t smem[];
    const uint32_t sbase = smem_u32(smem);
    const int tid = threadIdx.x;
    const int lid = tid & 31;
    const int wid = tid >> 5;
    const int wm = wid & 1;
    const int wn = wid >> 1;
    const int bm = blockIdx.y * 128;
    const int bn = blockIdx.x * 128;
    const int nch = K >> 5;

    const int ra = tid >> 1, ha = tid & 1;
    const size_t strA = (size_t)M * 128, strB = (size_t)Npad * 128;
    const uint8_t* srcA = Ac + (size_t)(bm + ra) * 128 + (size_t)ha * 64;
    const uint8_t* srcB = Bc + (size_t)(bn + ra) * 128 + (size_t)ha * 64;
    if (SPLIT) {
        srcA += (size_t)blockIdx.z * nch * strA;
        srcB += (size_t)blockIdx.z * nch * strB;
        C    += (size_t)blockIdx.z * M * N;
    }
    uint32_t doff[4];
    #pragma unroll
    for (int j = 0; j < 4; j++) {
        uint32_t o = (uint32_t)(ra * 128 + ha * 64 + j * 16);
        doff[j] = o ^ ((o >> 3) & 0x70);
    }

    auto issue = [&](int ch) {
        const uint32_t st = sbase + (uint32_t)(ch % NSTAGE) * STAGE_B;
        const uint8_t* sa = srcA + (size_t)ch * strA;
        const uint8_t* sb = srcB + (size_t)ch * strB;
        #pragma unroll
        for (int j = 0; j < 4; j++) {
            if (TERMS == 3 || ha == 0)          // A lo-half unused when TERMS==2
                cp16(st + doff[j], sa + j * 16);
            cp16(st + 16384 + doff[j], sb + j * 16);
        }
    };

    #pragma unroll
    for (int ch = 0; ch < 2; ch++) {
        if (ch < nch) issue(ch);
        asm volatile("cp.async.commit_group;" ::: "memory");
    }

    float acc[4][4][4];
    #pragma unroll
    for (int i = 0; i < 4; i++)
        #pragma unroll
        for (int j = 0; j < 4; j++)
            #pragma unroll
            for (int q = 0; q < 4; q++) acc[i][j][q] = 0.f;

    const int lrow = lid & 15;
    const uint32_t lo16 = (uint32_t)((lid >> 4) * 16);
    uint32_t aB[4], bB[2];
    #pragma unroll
    for (int mt = 0; mt < 4; mt++) {
        uint32_t x = (uint32_t)((wm * 64 + mt * 16 + lrow) * 128);
        aB[mt] = x ^ ((x >> 3) & 0x70);
    }
    #pragma unroll
    for (int p = 0; p < 2; p++) {
        uint32_t x = (uint32_t)((wn * 32 + p * 16 + lrow) * 128);
        bB[p] = x ^ ((x >> 3) & 0x70);
    }

    for (int ch = 0; ch < nch; ch++) {
        asm volatile("cp.async.wait_group 1;" ::: "memory");
        __syncthreads();
        if (ch + 2 < nch) issue(ch + 2);
        asm volatile("cp.async.commit_group;" ::: "memory");

        const uint32_t stA = sbase + (uint32_t)(ch % NSTAGE) * STAGE_B;
        const uint32_t stB = stA + 16384;
        #pragma unroll
        for (int s = 0; s < 2; s++) {
            const uint32_t sx = ((uint32_t)s << 5) ^ lo16;
            uint32_t bh[2][4], bl[2][4];
            #pragma unroll
            for (int p = 0; p < 2; p++) {
                ldsm4(bh[p], stB + (bB[p] ^ sx));
                ldsm4(bl[p], stB + (bB[p] ^ sx ^ 64));
            }
            #pragma unroll
            for (int mt = 0; mt < 4; mt++) {
                uint32_t ah[4], al[4];
                ldsm4(ah, stA + (aB[mt] ^ sx));
                if (TERMS == 3) ldsm4(al, stA + (aB[mt] ^ sx ^ 64));
                #pragma unroll
                for (int nt = 0; nt < 4; nt++) {
                    const int p = nt >> 1, q = nt & 1;
                    mma16816f(acc[mt][nt], ah, bh[p][q], bh[p][q + 2]);
                }
                #pragma unroll
                for (int nt = 0; nt < 4; nt++) {
                    const int p = nt >> 1, q = nt & 1;
                    mma16816f(acc[mt][nt], ah, bl[p][q], bl[p][q + 2]);
                }
                if (TERMS == 3) {
                    #pragma unroll
                    for (int nt = 0; nt < 4; nt++) {
                        const int p = nt >> 1, q = nt & 1;
                        mma16816f(acc[mt][nt], al, bh[p][q], bh[p][q + 2]);
                    }
                }
            }
        }
    }
    asm volatile("cp.async.wait_group 0;" ::: "memory");

    #pragma unroll
    for (int mt = 0; mt < 4; mt++) {
        const int m = bm + wm * 64 + mt * 16 + (lid >> 2);
        #pragma unroll
        for (int nt = 0; nt < 4; nt++) {
            const int n = bn + wn * 32 + nt * 8 + (lid & 3) * 2;
            if (n < N) {
                float v0 = acc[mt][nt][0], v1 = acc[mt][nt][1];
                float v2 = acc[mt][nt][2], v3 = acc[mt][nt][3];
                if (EPI == 1) {
                    v0 = softplusf(v0 + bias[n]);     v1 = softplusf(v1 + bias[n + 1]);
                    v2 = softplusf(v2 + bias[n]);     v3 = softplusf(v3 + bias[n + 1]);
                }
                *(float2*)(C + (size_t)m * N + n)       = make_float2(v0, v1);
                *(float2*)(C + (size_t)(m + 8) * N + n) = make_float2(v2, v3);
            }
        }
    }
}

// ---------------- x_proj split-K reduction: sum partials -> xdbl fp32 + xdt fp16-pair ----------------
__global__ void reduce_xproj(const float* __restrict__ part,
                             float* __restrict__ xdbl,
                             uint8_t* __restrict__ xdt)
{
    int idx = blockIdx.x * blockDim.x + threadIdx.x;
    if (idx >= MROWS * XDBLW) return;
    int m = idx / XDBLW, n = idx - m * XDBLW;
    float s = 0.f;
    #pragma unroll
    for (int p = 0; p < XSPLIT; p++)
        s += part[(size_t)p * MROWS * XDBLW + idx];
    xdbl[idx] = s;
    if (n < DTRANK) {
        __half hi, lo;
        split_f16(s, hi, lo);
        uint8_t* q = xdt + ((size_t)(n >> 5) * MROWS + m) * 128 + (n & 31) * 2;
        *(__half*)q        = hi;
        *(__half*)(q + 64) = lo;
    }
}

// ---------------- causal depthwise conv (K=4) + SiLU, fp32 + fp16-pair outputs ----------------
__global__ void conv_silu_kernel(const float* __restrict__ xz,
                                 const float* __restrict__ cw,
                                 const float* __restrict__ cb,
                                 float* __restrict__ xc,
                                 uint8_t* __restrict__ xcc)
{
    int idx = blockIdx.x * blockDim.x + threadIdx.x;
    int d  = idx & (DINNER - 1);
    int bl = idx / DINNER;
    int l  = bl & (SEQLEN - 1);

    float acc = cb[d];
    #pragma unroll
    for (int k = 0; k < DCONV; k++) {
        int li = l + k - (DCONV - 1);
        if (li >= 0) {
            float xv = xz[((size_t)(bl + (li - l))) * 2 * DINNER + d];
            acc = fmaf(xv, cw[d * DCONV + k], acc);
        }
    }
    float v = siluf(acc);
    xc[idx] = v;
    __half hi, lo;
    split_f16(v, hi, lo);
    uint8_t* p = xcc + ((size_t)(d >> 5) * MROWS + bl) * 128 + (d & 31) * 2;
    *(__half*)p        = hi;
    *(__half*)(p + 64) = lo;
}

// ---------------- selective scan: cp.async staged, double-buffered ----------------
#define SC_T 16
__global__ void __launch_bounds__(64)
scan_kernel(const float* __restrict__ delta,
            const float* __restrict__ xc,
            const float* __restrict__ xz,
            const float* __restrict__ xdbl,
            const float* __restrict__ A,
            const float* __restrict__ Dp,
            uint8_t* __restrict__ yc)
{
    const int tid = threadIdx.x;
    const int d0 = blockIdx.x * 64;
    const int d  = d0 + tid;
    const int b  = blockIdx.y;

    // 16B alignment REQUIRED for cp.async destinations
    __shared__ __align__(16) float sD[2][SC_T][64];
    __shared__ __align__(16) float sX[2][SC_T][64];
    __shared__ __align__(16) float sZ[2][SC_T][64];
    __shared__ __align__(16) float sB[2][SC_T][16];
    __shared__ __align__(16) float sC[2][SC_T][16];

    float st[DSTATE], a[DSTATE];
    #pragma unroll
    for (int n = 0; n < DSTATE; n++) {
        st[n] = 0.f;
        a[n]  = A[(size_t)d * DSTATE + n];
    }
    const float Dd = Dp[d];
    const float a0 = a[0];
    bool fast = true;
    #pragma unroll
    for (int n = 0; n < DSTATE; n++) fast = fast && (a[n] == a0 * (n + 1));

    uint8_t* ycb = yc + (size_t)(d >> 5) * MROWS * 128 + (d & 31) * 2;

    auto stage = [&](int buf, int t0) {
        #pragma unroll
        for (int j = tid; j < SC_T * 16; j += 64) {
            int row = j >> 4, sec = j & 15;
            size_t r = (size_t)(b * SEQLEN + t0 + row);
            cp16(smem_u32(&sD[buf][row][sec * 4]), delta + r * DINNER + d0 + sec * 4);
            cp16(smem_u32(&sX[buf][row][sec * 4]), xc + r * DINNER + d0 + sec * 4);
            cp16(smem_u32(&sZ[buf][row][sec * 4]), xz + r * 2 * DINNER + DINNER + d0 + sec * 4);
        }
        {
            int row = tid >> 2, sec = tid & 3;   // 64 = SC_T*4 exactly
            size_t r = (size_t)(b * SEQLEN + t0 + row);
            cp16(smem_u32(&sB[buf][row][sec * 4]), xdbl + r * XDBLW + DTRANK + sec * 4);
            cp16(smem_u32(&sC[buf][row][sec * 4]), xdbl + r * XDBLW + DTRANK + DSTATE + sec * 4);
        }
    };

    stage(0, 0);
    asm volatile("cp.async.commit_group;" ::: "memory");
    int buf = 0;

    for (int ch = 0; ch < SEQLEN / SC_T; ch++) {
        if (ch + 1 < SEQLEN / SC_T) stage(buf ^ 1, (ch + 1) * SC_T);
        asm volatile("cp.async.commit_group;" ::: "memory");
        asm volatile("cp.async.wait_group 1;" ::: "memory");
        __syncthreads();

        const int t0 = ch * SC_T;
        #pragma unroll 4
        for (int tt = 0; tt < SC_T; tt++) {
            float dlt = sD[buf][tt][tid];
            float xv  = sX[buf][tt][tid];
            float zv  = sZ[buf][tt][tid];
            float dx  = dlt * xv;
            float e[DSTATE];
            if (fast) {
                float p  = __expf(dlt * a0);
                float p2 = p * p, p3 = p2 * p, p4 = p2 * p2, p8 = p4 * p4;
                e[0] = p;       e[1] = p2;      e[2] = p3;      e[3] = p4;
                e[4] = p4 * p;  e[5] = p4 * p2; e[6] = p4 * p3; e[7] = p8;
                e[8] = p8 * p;  e[9] = p8 * p2; e[10] = p8 * p3; e[11] = p8 * p4;
                e[12] = e[8] * p4; e[13] = e[9] * p4; e[14] = e[10] * p4; e[15] = p8 * p8;
            } else {
                #pragma unroll
                for (int n = 0; n < DSTATE; n++) e[n] = __expf(dlt * a[n]);
            }
            float yv = 0.f;
            #pragma unroll
            for (int n = 0; n < DSTATE; n++) {
                st[n] = fmaf(e[n], st[n], dx * sB[buf][tt][n]);
                yv    = fmaf(st[n], sC[buf][tt][n], yv);
            }
            float outv = (yv + xv * Dd) * siluf(zv);
            __half hi, lo;
            split_f16(outv, hi, lo);
            uint8_t* p = ycb + (size_t)(b * SEQLEN + t0 + tt) * 128;
            *(__half*)p        = hi;
            *(__half*)(p + 64) = lo;
        }
        __syncthreads();
        buf ^= 1;
    }
}

// ---------------- launch ----------------
extern "C" void kernel_launch(void* const* d_in, const int* in_sizes, int n_in,
                              void* d_out, int out_size)
{
    const float* hidden     = (const float*)d_in[0];
    const float* in_proj_w  = (const float*)d_in[1];
    const float* conv_w     = (const float*)d_in[2];
    const float* conv_b     = (const float*)d_in[3];
    const float* x_proj_w   = (const float*)d_in[4];
    const float* dt_proj_w  = (const float*)d_in[5];
    const float* dt_proj_b  = (const float*)d_in[6];
    const float* out_proj_w = (const float*)d_in[7];
    const float* A_in       = (const float*)d_in[8];
    const float* D_param    = (const float*)d_in[9];
    float* out = (float*)d_out;

    static float *p_xz = nullptr, *p_xc = nullptr, *p_xdbl = nullptr,
                 *p_xpart = nullptr, *p_delta = nullptr, *p_dummy = nullptr;
    static uint8_t *p_hidc, *p_winc, *p_xcc, *p_wxpc, *p_xdtc, *p_wdtc, *p_yc, *p_woutc;
    static bool init_done = false;
    if (!init_done) {
        cudaGetSymbolAddress((void**)&p_xz,    g_xz);
        cudaGetSymbolAddress((void**)&p_xc,    g_xc);
        cudaGetSymbolAddress((void**)&p_xdbl,  g_xdbl);
        cudaGetSymbolAddress((void**)&p_xpart, g_xpart);
        cudaGetSymbolAddress((void**)&p_delta, g_delta);
        cudaGetSymbolAddress((void**)&p_dummy, g_dummy);
        cudaGetSymbolAddress((void**)&p_hidc,  g_hid_c);
        cudaGetSymbolAddress((void**)&p_winc,  g_win_c);
        cudaGetSymbolAddress((void**)&p_xcc,   g_xc_c);
        cudaGetSymbolAddress((void**)&p_wxpc,  g_wxp_c);
        cudaGetSymbolAddress((void**)&p_xdtc,  g_xdt_c);
        cudaGetSymbolAddress((void**)&p_wdtc,  g_wdt_c);
        cudaGetSymbolAddress((void**)&p_yc,    g_y_c);
        cudaGetSymbolAddress((void**)&p_woutc, g_wout_c);
        cudaFuncSetAttribute((const void*)gemm_ca<0,0,2>, cudaFuncAttributeMaxDynamicSharedMemorySize, GEMM_SMEM);
        cudaFuncSetAttribute((const void*)gemm_ca<1,0,3>, cudaFuncAttributeMaxDynamicSharedMemorySize, GEMM_SMEM);
        cudaFuncSetAttribute((const void*)gemm_ca<0,1,3>, cudaFuncAttributeMaxDynamicSharedMemorySize, GEMM_SMEM);
        init_done = true;
    }

    // #1, #2 converts; #3 nop -> in_proj at captured launch #4
    convert_kernel<<<(MROWS * (DMODEL >> 3) + 255) / 256, 256>>>(hidden, DMODEL, MROWS, MROWS, DMODEL, p_hidc);
    convert_kernel<<<(2 * DINNER * (DMODEL >> 3) + 255) / 256, 256>>>(in_proj_w, DMODEL, 2 * DINNER, 2 * DINNER, DMODEL, p_winc);
    nop_kernel<<<1, 32>>>(p_dummy);

    // #4) in_proj -> xz (fp32), 2-term
    gemm_ca<0,0,2><<<dim3(2 * DINNER / 128, MROWS / 128), 256, GEMM_SMEM>>>(
        p_hidc, p_winc, nullptr, p_xz, MROWS, 2 * DINNER, 2 * DINNER, DMODEL);

    // conv + SiLU -> xc (fp32) + xcc (fp16-pair)
    conv_silu_kernel<<<(MROWS * DINNER) / 256, 256>>>(p_xz, conv_w, conv_b, p_xc, p_xcc);

    // x_proj: split-K x8 (3-term) -> partials -> reduce (also emits xdt fp16-pair)
    convert_kernel<<<(256 * (DINNER >> 3) + 255) / 256, 256>>>(x_proj_w, DINNER, XDBLW, 256, DINNER, p_wxpc);
    gemm_ca<0,1,3><<<dim3(2, MROWS / 128, XSPLIT), 256, GEMM_SMEM>>>(
        p_xcc, p_wxpc, nullptr, p_xpart, MROWS, 256, XDBLW, DINNER / XSPLIT);
    reduce_xproj<<<(MROWS * XDBLW + 255) / 256, 256>>>(p_xpart, p_xdbl, p_xdtc);

    // dt_proj + bias + softplus -> delta (fp32), 3-term
    convert_kernel<<<(DINNER * (DTRANK >> 3) + 255) / 256, 256>>>(dt_proj_w, DTRANK, DINNER, DINNER, DTRANK, p_wdtc);
    gemm_ca<1,0,3><<<dim3(DINNER / 128, MROWS / 128), 256, GEMM_SMEM>>>(
        p_xdtc, p_wdtc, dt_proj_b, p_delta, MROWS, DINNER, DINNER, DTRANK);

    // scan -> yc (fp16-pair)
    scan_kernel<<<dim3(DINNER / 64, BATCH), 64>>>(
        p_delta, p_xc, p_xz, p_xdbl, A_in, D_param, p_yc);

    // out_proj, 2-term
    convert_kernel<<<(DMODEL * (DINNER >> 3) + 255) / 256, 256>>>(out_proj_w, DINNER, DMODEL, DMODEL, DINNER, p_woutc);
    gemm_ca<0,0,2><<<dim3(DMODEL / 128, MROWS / 128), 256, GEMM_SMEM>>>(
        p_yc, p_woutc, nullptr, out, MROWS, DMODEL, DMODEL, DINNER);
}

// round 17
// speedup vs baseline: 1.9113x; 1.0482x over previous
#include <cuda_runtime.h>
#include <cuda_fp16.h>
#include <cstdint>
#include <cstddef>

// R17: byte-identical resubmission of R16 (infra failure, first occurrence for
// this source — matches the R4/R9 flake pattern; code re-audited clean).
// (1) tiled convert kernel with fully-coalesced writes;
// (2) GEMM hoists all B fragments per chunk (cross-s ILP).
// Numerics unchanged from R15 (2-term in/out_proj, 3-term x/dt).

// Problem constants
#define BATCH   2
#define SEQLEN  1024
#define DMODEL  2048
#define DINNER  4096
#define DSTATE  16
#define DTRANK  128
#define DCONV   4
#define MROWS   (BATCH * SEQLEN)          // 2048
#define XDBLW   (DTRANK + 2 * DSTATE)     // 160
#define XSPLIT  8                          // split-K ways for x_proj

// ---------------- fp32 scratch ----------------
__device__ float g_xz[(size_t)MROWS * 2 * DINNER];
__device__ float g_xc[(size_t)MROWS * DINNER];
__device__ float g_xdbl[(size_t)MROWS * XDBLW];
__device__ float g_xpart[(size_t)XSPLIT * MROWS * XDBLW];
__device__ float g_delta[(size_t)MROWS * DINNER];
__device__ float g_dummy[32];

// ---------------- fp16-pair scratch: [K/32][rows][128B] (32 hi fp16 | 32 lo fp16) ----------------
__device__ uint4 g_hid_c [(size_t)MROWS  * DMODEL / 4];
__device__ uint4 g_win_c [(size_t)2 * DINNER * DMODEL / 4];
__device__ uint4 g_xc_c  [(size_t)MROWS  * DINNER / 4];
__device__ uint4 g_wxp_c [(size_t)256    * DINNER / 4];
__device__ uint4 g_xdt_c [(size_t)MROWS  * DTRANK / 4];
__device__ uint4 g_wdt_c [(size_t)DINNER * DTRANK / 4];
__device__ uint4 g_y_c   [(size_t)MROWS  * DINNER / 4];
__device__ uint4 g_wout_c[(size_t)DMODEL * DINNER / 4];

// ---------------- helpers ----------------
__device__ __forceinline__ uint32_t smem_u32(const void* p) {
    uint32_t a;
    asm("{ .reg .u64 t; cvta.to.shared.u64 t, %1; cvt.u32.u64 %0, t; }" : "=r"(a) : "l"(p));
    return a;
}
__device__ __forceinline__ float softplusf(float x) {
    return x > 20.f ? x : log1pf(__expf(x));
}
__device__ __forceinline__ float siluf(float x) {
    return x / (1.f + __expf(-x));
}
__device__ __forceinline__ void split_f16(float v, __half& hi, __half& lo) {
    hi = __float2half_rn(v);
    lo = __float2half_rn(v - __half2float(hi));
}
__device__ __forceinline__ uint32_t pack_h2(__half a, __half b) {
    return (uint32_t)__half_as_ushort(a) | ((uint32_t)__half_as_ushort(b) << 16);
}

__device__ __forceinline__ void ldsm4(uint32_t (&r)[4], uint32_t addr) {
    asm volatile("ldmatrix.sync.aligned.m8n8.x4.shared.b16 {%0,%1,%2,%3}, [%4];"
                 : "=r"(r[0]), "=r"(r[1]), "=r"(r[2]), "=r"(r[3]) : "r"(addr));
}
__device__ __forceinline__ void mma16816f(float (&c)[4], const uint32_t (&a)[4],
                                          uint32_t b0, uint32_t b1) {
    asm volatile(
        "mma.sync.aligned.m16n8k16.row.col.f32.f16.f16.f32 "
        "{%0,%1,%2,%3}, {%4,%5,%6,%7}, {%8,%9}, {%0,%1,%2,%3};"
        : "+f"(c[0]), "+f"(c[1]), "+f"(c[2]), "+f"(c[3])
        : "r"(a[0]), "r"(a[1]), "r"(a[2]), "r"(a[3]), "r"(b0), "r"(b1));
}
__device__ __forceinline__ void cp16(uint32_t dst, const void* src) {
    asm volatile("cp.async.cg.shared.global [%0], [%1], 16;" :: "r"(dst), "l"(src));
}

__global__ void nop_kernel(float* p) {
    if (threadIdx.x == 0) p[blockIdx.x] = 0.f;
}

// ---------------- convert v2: fp32 (rows x K, stride ld) -> fp16-pair [K/32][npad][128B] ----------------
// grid = (npad/64, K/32), block 256. 4 threads per row (8 elems each).
// Warp covers 8 rows: writes 8 full 128B dst rows = 1KB contiguous.
__global__ void convert2_kernel(const float* __restrict__ src, int ld, int nvalid,
                                int npad, uint8_t* __restrict__ dst)
{
    const int r  = blockIdx.x * 64 + (threadIdx.x >> 2);
    const int kc = blockIdx.y;
    const int kk = (threadIdx.x & 3) * 8;
    float4 v0 = make_float4(0.f, 0.f, 0.f, 0.f), v1 = v0;
    if (r < nvalid) {
        const float* s = src + (size_t)r * ld + kc * 32 + kk;
        v0 = *(const float4*)(s);
        v1 = *(const float4*)(s + 4);
    }
    __half h[8], l[8];
    split_f16(v0.x, h[0], l[0]); split_f16(v0.y, h[1], l[1]);
    split_f16(v0.z, h[2], l[2]); split_f16(v0.w, h[3], l[3]);
    split_f16(v1.x, h[4], l[4]); split_f16(v1.y, h[5], l[5]);
    split_f16(v1.z, h[6], l[6]); split_f16(v1.w, h[7], l[7]);
    uint4 hi = make_uint4(pack_h2(h[0], h[1]), pack_h2(h[2], h[3]),
                          pack_h2(h[4], h[5]), pack_h2(h[6], h[7]));
    uint4 lo = make_uint4(pack_h2(l[0], l[1]), pack_h2(l[2], l[3]),
                          pack_h2(l[4], l[5]), pack_h2(l[6], l[7]));
    size_t off = ((size_t)kc * npad + r) * 128 + kk * 2;
    *(uint4*)(dst + off)      = hi;
    *(uint4*)(dst + off + 64) = lo;
}

// ---------------- GEMM: cp.async 3-stage, 2 CTAs/SM, fp16-pair operands ----------------
// TERMS=3: ah*bh + ah*bl + al*bh ; TERMS=2: ah*bh + ah*bl (A residual dropped)
// SPLIT=1: blockIdx.z selects a K/XSPLIT-wide K slice; raw partials to C + z*M*N.
#define NSTAGE  3
#define STAGE_B 32768
#define GEMM_SMEM (NSTAGE * STAGE_B)   // 96KB

template <int EPI, int SPLIT, int TERMS>
__global__ void __launch_bounds__(256, 2)
gemm_ca(const uint8_t* __restrict__ Ac, const uint8_t* __restrict__ Bc,
        const float* __restrict__ bias, float* __restrict__ C,
        int M, int Npad, int N, int K)
{
    extern __shared__ __align__(1024) uint8_t smem[];
    const uint32_t sbase = smem_u32(smem);
    const int tid = threadIdx.x;
    const int lid = tid & 31;
    const int wid = tid >> 5;
    const int wm = wid & 1;
    const int wn = wid >> 1;
    const int bm = blockIdx.y * 128;
    const int bn = blockIdx.x * 128;
    const int nch = K >> 5;

    const int ra = tid >> 1, ha = tid & 1;
    const size_t strA = (size_t)M * 128, strB = (size_t)Npad * 128;
    const uint8_t* srcA = Ac + (size_t)(bm + ra) * 128 + (size_t)ha * 64;
    const uint8_t* srcB = Bc + (size_t)(bn + ra) * 128 + (size_t)ha * 64;
    if (SPLIT) {
        srcA += (size_t)blockIdx.z * nch * strA;
        srcB += (size_t)blockIdx.z * nch * strB;
        C    += (size_t)blockIdx.z * M * N;
    }
    uint32_t doff[4];
    #pragma unroll
    for (int j = 0; j < 4; j++) {
        uint32_t o = (uint32_t)(ra * 128 + ha * 64 + j * 16);
        doff[j] = o ^ ((o >> 3) & 0x70);
    }

    auto issue = [&](int ch) {
        const uint32_t st = sbase + (uint32_t)(ch % NSTAGE) * STAGE_B;
        const uint8_t* sa = srcA + (size_t)ch * strA;
        const uint8_t* sb = srcB + (size_t)ch * strB;
        #pragma unroll
        for (int j = 0; j < 4; j++) {
            if (TERMS == 3 || ha == 0)          // A lo-half unused when TERMS==2
                cp16(st + doff[j], sa + j * 16);
            cp16(st + 16384 + doff[j], sb + j * 16);
        }
    };

    #pragma unroll
    for (int ch = 0; ch < 2; ch++) {
        if (ch < nch) issue(ch);
        asm volatile("cp.async.commit_group;" ::: "memory");
    }

    float acc[4][4][4];
    #pragma unroll
    for (int i = 0; i < 4; i++)
        #pragma unroll
        for (int j = 0; j < 4; j++)
            #pragma unroll
            for (int q = 0; q < 4; q++) acc[i][j][q] = 0.f;

    const int lrow = lid & 15;
    const uint32_t lo16 = (uint32_t)((lid >> 4) * 16);
    uint32_t aB[4], bB[2];
    #pragma unroll
    for (int mt = 0; mt < 4; mt++) {
        uint32_t x = (uint32_t)((wm * 64 + mt * 16 + lrow) * 128);
        aB[mt] = x ^ ((x >> 3) & 0x70);
    }
    #pragma unroll
    for (int p = 0; p < 2; p++) {
        uint32_t x = (uint32_t)((wn * 32 + p * 16 + lrow) * 128);
        bB[p] = x ^ ((x >> 3) & 0x70);
    }

    for (int ch = 0; ch < nch; ch++) {
        asm volatile("cp.async.wait_group 1;" ::: "memory");
        __syncthreads();
        if (ch + 2 < nch) issue(ch + 2);
        asm volatile("cp.async.commit_group;" ::: "memory");

        const uint32_t stA = sbase + (uint32_t)(ch % NSTAGE) * STAGE_B;
        const uint32_t stB = stA + 16384;

        // hoist ALL B fragments for both k16 steps of this chunk (cross-s ILP)
        uint32_t bh[2][2][4], bl[2][2][4];
        #pragma unroll
        for (int s = 0; s < 2; s++) {
            const uint32_t sx = ((uint32_t)s << 5) ^ lo16;
            #pragma unroll
            for (int p = 0; p < 2; p++) {
                ldsm4(bh[s][p], stB + (bB[p] ^ sx));
                ldsm4(bl[s][p], stB + (bB[p] ^ sx ^ 64));
            }
        }
        #pragma unroll
        for (int s = 0; s < 2; s++) {
            const uint32_t sx = ((uint32_t)s << 5) ^ lo16;
            #pragma unroll
            for (int mt = 0; mt < 4; mt++) {
                uint32_t ah[4], al[4];
                ldsm4(ah, stA + (aB[mt] ^ sx));
                if (TERMS == 3) ldsm4(al, stA + (aB[mt] ^ sx ^ 64));
                #pragma unroll
                for (int nt = 0; nt < 4; nt++) {
                    const int p = nt >> 1, q = nt & 1;
                    mma16816f(acc[mt][nt], ah, bh[s][p][q], bh[s][p][q + 2]);
                }
                #pragma unroll
                for (int nt = 0; nt < 4; nt++) {
                    const int p = nt >> 1, q = nt & 1;
                    mma16816f(acc[mt][nt], ah, bl[s][p][q], bl[s][p][q + 2]);
                }
                if (TERMS == 3) {
                    #pragma unroll
                    for (int nt = 0; nt < 4; nt++) {
                        const int p = nt >> 1, q = nt & 1;
                        mma16816f(acc[mt][nt], al, bh[s][p][q], bh[s][p][q + 2]);
                    }
                }
            }
        }
    }
    asm volatile("cp.async.wait_group 0;" ::: "memory");

    #pragma unroll
    for (int mt = 0; mt < 4; mt++) {
        const int m = bm + wm * 64 + mt * 16 + (lid >> 2);
        #pragma unroll
        for (int nt = 0; nt < 4; nt++) {
            const int n = bn + wn * 32 + nt * 8 + (lid & 3) * 2;
            if (n < N) {
                float v0 = acc[mt][nt][0], v1 = acc[mt][nt][1];
                float v2 = acc[mt][nt][2], v3 = acc[mt][nt][3];
                if (EPI == 1) {
                    v0 = softplusf(v0 + bias[n]);     v1 = softplusf(v1 + bias[n + 1]);
                    v2 = softplusf(v2 + bias[n]);     v3 = softplusf(v3 + bias[n + 1]);
                }
                *(float2*)(C + (size_t)m * N + n)       = make_float2(v0, v1);
                *(float2*)(C + (size_t)(m + 8) * N + n) = make_float2(v2, v3);
            }
        }
    }
}

// ---------------- x_proj split-K reduction: sum partials -> xdbl fp32 + xdt fp16-pair ----------------
__global__ void reduce_xproj(const float* __restrict__ part,
                             float* __restrict__ xdbl,
                             uint8_t* __restrict__ xdt)
{
    int idx = blockIdx.x * blockDim.x + threadIdx.x;
    if (idx >= MROWS * XDBLW) return;
    int m = idx / XDBLW, n = idx - m * XDBLW;
    float s = 0.f;
    #pragma unroll
    for (int p = 0; p < XSPLIT; p++)
        s += part[(size_t)p * MROWS * XDBLW + idx];
    xdbl[idx] = s;
    if (n < DTRANK) {
        __half hi, lo;
        split_f16(s, hi, lo);
        uint8_t* q = xdt + ((size_t)(n >> 5) * MROWS + m) * 128 + (n & 31) * 2;
        *(__half*)q        = hi;
        *(__half*)(q + 64) = lo;
    }
}

// ---------------- causal depthwise conv (K=4) + SiLU, fp32 + fp16-pair outputs ----------------
__global__ void conv_silu_kernel(const float* __restrict__ xz,
                                 const float* __restrict__ cw,
                                 const float* __restrict__ cb,
                                 float* __restrict__ xc,
                                 uint8_t* __restrict__ xcc)
{
    int idx = blockIdx.x * blockDim.x + threadIdx.x;
    int d  = idx & (DINNER - 1);
    int bl = idx / DINNER;
    int l  = bl & (SEQLEN - 1);

    float acc = cb[d];
    #pragma unroll
    for (int k = 0; k < DCONV; k++) {
        int li = l + k - (DCONV - 1);
        if (li >= 0) {
            float xv = xz[((size_t)(bl + (li - l))) * 2 * DINNER + d];
            acc = fmaf(xv, cw[d * DCONV + k], acc);
        }
    }
    float v = siluf(acc);
    xc[idx] = v;
    __half hi, lo;
    split_f16(v, hi, lo);
    uint8_t* p = xcc + ((size_t)(d >> 5) * MROWS + bl) * 128 + (d & 31) * 2;
    *(__half*)p        = hi;
    *(__half*)(p + 64) = lo;
}

// ---------------- selective scan: cp.async staged, double-buffered ----------------
#define SC_T 16
__global__ void __launch_bounds__(64)
scan_kernel(const float* __restrict__ delta,
            const float* __restrict__ xc,
            const float* __restrict__ xz,
            const float* __restrict__ xdbl,
            const float* __restrict__ A,
            const float* __restrict__ Dp,
            uint8_t* __restrict__ yc)
{
    const int tid = threadIdx.x;
    const int d0 = blockIdx.x * 64;
    const int d  = d0 + tid;
    const int b  = blockIdx.y;

    // 16B alignment REQUIRED for cp.async destinations
    __shared__ __align__(16) float sD[2][SC_T][64];
    __shared__ __align__(16) float sX[2][SC_T][64];
    __shared__ __align__(16) float sZ[2][SC_T][64];
    __shared__ __align__(16) float sB[2][SC_T][16];
    __shared__ __align__(16) float sC[2][SC_T][16];

    float st[DSTATE], a[DSTATE];
    #pragma unroll
    for (int n = 0; n < DSTATE; n++) {
        st[n] = 0.f;
        a[n]  = A[(size_t)d * DSTATE + n];
    }
    const float Dd = Dp[d];
    const float a0 = a[0];
    bool fast = true;
    #pragma unroll
    for (int n = 0; n < DSTATE; n++) fast = fast && (a[n] == a0 * (n + 1));

    uint8_t* ycb = yc + (size_t)(d >> 5) * MROWS * 128 + (d & 31) * 2;

    auto stage = [&](int buf, int t0) {
        #pragma unroll
        for (int j = tid; j < SC_T * 16; j += 64) {
            int row = j >> 4, sec = j & 15;
            size_t r = (size_t)(b * SEQLEN + t0 + row);
            cp16(smem_u32(&sD[buf][row][sec * 4]), delta + r * DINNER + d0 + sec * 4);
            cp16(smem_u32(&sX[buf][row][sec * 4]), xc + r * DINNER + d0 + sec * 4);
            cp16(smem_u32(&sZ[buf][row][sec * 4]), xz + r * 2 * DINNER + DINNER + d0 + sec * 4);
        }
        {
            int row = tid >> 2, sec = tid & 3;   // 64 = SC_T*4 exactly
            size_t r = (size_t)(b * SEQLEN + t0 + row);
            cp16(smem_u32(&sB[buf][row][sec * 4]), xdbl + r * XDBLW + DTRANK + sec * 4);
            cp16(smem_u32(&sC[buf][row][sec * 4]), xdbl + r * XDBLW + DTRANK + DSTATE + sec * 4);
        }
    };

    stage(0, 0);
    asm volatile("cp.async.commit_group;" ::: "memory");
    int buf = 0;

    for (int ch = 0; ch < SEQLEN / SC_T; ch++) {
        if (ch + 1 < SEQLEN / SC_T) stage(buf ^ 1, (ch + 1) * SC_T);
        asm volatile("cp.async.commit_group;" ::: "memory");
        asm volatile("cp.async.wait_group 1;" ::: "memory");
        __syncthreads();

        const int t0 = ch * SC_T;
        #pragma unroll 4
        for (int tt = 0; tt < SC_T; tt++) {
            float dlt = sD[buf][tt][tid];
            float xv  = sX[buf][tt][tid];
            float zv  = sZ[buf][tt][tid];
            float dx  = dlt * xv;
            float e[DSTATE];
            if (fast) {
                float p  = __expf(dlt * a0);
                float p2 = p * p, p3 = p2 * p, p4 = p2 * p2, p8 = p4 * p4;
                e[0] = p;       e[1] = p2;      e[2] = p3;      e[3] = p4;
                e[4] = p4 * p;  e[5] = p4 * p2; e[6] = p4 * p3; e[7] = p8;
                e[8] = p8 * p;  e[9] = p8 * p2; e[10] = p8 * p3; e[11] = p8 * p4;
                e[12] = e[8] * p4; e[13] = e[9] * p4; e[14] = e[10] * p4; e[15] = p8 * p8;
            } else {
                #pragma unroll
                for (int n = 0; n < DSTATE; n++) e[n] = __expf(dlt * a[n]);
            }
            float yv = 0.f;
            #pragma unroll
            for (int n = 0; n < DSTATE; n++) {
                st[n] = fmaf(e[n], st[n], dx * sB[buf][tt][n]);
                yv    = fmaf(st[n], sC[buf][tt][n], yv);
            }
            float outv = (yv + xv * Dd) * siluf(zv);
            __half hi, lo;
            split_f16(outv, hi, lo);
            uint8_t* p = ycb + (size_t)(b * SEQLEN + t0 + tt) * 128;
            *(__half*)p        = hi;
            *(__half*)(p + 64) = lo;
        }
        __syncthreads();
        buf ^= 1;
    }
}

// ---------------- launch ----------------
extern "C" void kernel_launch(void* const* d_in, const int* in_sizes, int n_in,
                              void* d_out, int out_size)
{
    const float* hidden     = (const float*)d_in[0];
    const float* in_proj_w  = (const float*)d_in[1];
    const float* conv_w     = (const float*)d_in[2];
    const float* conv_b     = (const float*)d_in[3];
    const float* x_proj_w   = (const float*)d_in[4];
    const float* dt_proj_w  = (const float*)d_in[5];
    const float* dt_proj_b  = (const float*)d_in[6];
    const float* out_proj_w = (const float*)d_in[7];
    const float* A_in       = (const float*)d_in[8];
    const float* D_param    = (const float*)d_in[9];
    float* out = (float*)d_out;

    static float *p_xz = nullptr, *p_xc = nullptr, *p_xdbl = nullptr,
                 *p_xpart = nullptr, *p_delta = nullptr, *p_dummy = nullptr;
    static uint8_t *p_hidc, *p_winc, *p_xcc, *p_wxpc, *p_xdtc, *p_wdtc, *p_yc, *p_woutc;
    static bool init_done = false;
    if (!init_done) {
        cudaGetSymbolAddress((void**)&p_xz,    g_xz);
        cudaGetSymbolAddress((void**)&p_xc,    g_xc);
        cudaGetSymbolAddress((void**)&p_xdbl,  g_xdbl);
        cudaGetSymbolAddress((void**)&p_xpart, g_xpart);
        cudaGetSymbolAddress((void**)&p_delta, g_delta);
        cudaGetSymbolAddress((void**)&p_dummy, g_dummy);
        cudaGetSymbolAddress((void**)&p_hidc,  g_hid_c);
        cudaGetSymbolAddress((void**)&p_winc,  g_win_c);
        cudaGetSymbolAddress((void**)&p_xcc,   g_xc_c);
        cudaGetSymbolAddress((void**)&p_wxpc,  g_wxp_c);
        cudaGetSymbolAddress((void**)&p_xdtc,  g_xdt_c);
        cudaGetSymbolAddress((void**)&p_wdtc,  g_wdt_c);
        cudaGetSymbolAddress((void**)&p_yc,    g_y_c);
        cudaGetSymbolAddress((void**)&p_woutc, g_wout_c);
        cudaFuncSetAttribute((const void*)gemm_ca<0,0,2>, cudaFuncAttributeMaxDynamicSharedMemorySize, GEMM_SMEM);
        cudaFuncSetAttribute((const void*)gemm_ca<1,0,3>, cudaFuncAttributeMaxDynamicSharedMemorySize, GEMM_SMEM);
        cudaFuncSetAttribute((const void*)gemm_ca<0,1,3>, cudaFuncAttributeMaxDynamicSharedMemorySize, GEMM_SMEM);
        init_done = true;
    }

    // #1, #2 converts; #3 nop -> in_proj at captured launch #4
    convert2_kernel<<<dim3(MROWS / 64, DMODEL / 32), 256>>>(hidden, DMODEL, MROWS, MROWS, p_hidc);
    convert2_kernel<<<dim3(2 * DINNER / 64, DMODEL / 32), 256>>>(in_proj_w, DMODEL, 2 * DINNER, 2 * DINNER, p_winc);
    nop_kernel<<<1, 32>>>(p_dummy);

    // #4) in_proj -> xz (fp32), 2-term
    gemm_ca<0,0,2><<<dim3(2 * DINNER / 128, MROWS / 128), 256, GEMM_SMEM>>>(
        p_hidc, p_winc, nullptr, p_xz, MROWS, 2 * DINNER, 2 * DINNER, DMODEL);

    // conv + SiLU -> xc (fp32) + xcc (fp16-pair)
    conv_silu_kernel<<<(MROWS * DINNER) / 256, 256>>>(p_xz, conv_w, conv_b, p_xc, p_xcc);

    // x_proj: split-K x8 (3-term) -> partials -> reduce (also emits xdt fp16-pair)
    convert2_kernel<<<dim3(256 / 64, DINNER / 32), 256>>>(x_proj_w, DINNER, XDBLW, 256, p_wxpc);
    gemm_ca<0,1,3><<<dim3(2, MROWS / 128, XSPLIT), 256, GEMM_SMEM>>>(
        p_xcc, p_wxpc, nullptr, p_xpart, MROWS, 256, XDBLW, DINNER / XSPLIT);
    reduce_xproj<<<(MROWS * XDBLW + 255) / 256, 256>>>(p_xpart, p_xdbl, p_xdtc);

    // dt_proj + bias + softplus -> delta (fp32), 3-term
    convert2_kernel<<<dim3(DINNER / 64, DTRANK / 32), 256>>>(dt_proj_w, DTRANK, DINNER, DINNER, p_wdtc);
    gemm_ca<1,0,3><<<dim3(DINNER / 128, MROWS / 128), 256, GEMM_SMEM>>>(
        p_xdtc, p_wdtc, dt_proj_b, p_delta, MROWS, DINNER, DINNER, DTRANK);

    // scan -> yc (fp16-pair)
    scan_kernel<<<dim3(DINNER / 64, BATCH), 64>>>(
        p_delta, p_xc, p_xz, p_xdbl, A_in, D_param, p_yc);

    // out_proj, 2-term
    convert2_kernel<<<dim3(DMODEL / 64, DINNER / 32), 256>>>(out_proj_w, DINNER, DMODEL, DMODEL, p_woutc);
    gemm_ca<0,0,2><<<dim3(DMODEL / 128, MROWS / 128), 256, GEMM_SMEM>>>(
        p_yc, p_woutc, nullptr, out, MROWS, DMODEL, DMODEL, DINNER);
}